// round 16
// baseline (speedup 1.0000x reference)
#include <cuda_runtime.h>
#include <cuda_fp16.h>
#include <cstdint>

#define B_    2
#define QLEN  900
#define DIMV  256
#define NH    8
#define HD    32
#define KVLEN 4096
#define GRD   64
#define RPEH  512
#define L2E   1.4426950408889634f
#define NQT   15          // q tiles of 64
#define NSPL  4           // kv splits

// ---------------- scratch ----------------
__device__ __half d_Qh[B_*NH*QLEN*HD];
__device__ __half d_Kh[B_*NH*KVLEN*HD];
__device__ __half d_Vh[B_*NH*KVLEN*HD];
__device__ __half d_ctxh[B_*QLEN*DIMV];
__device__ float  d_rpex[B_*NH*QLEN*GRD];
__device__ float  d_rpey[B_*NH*QLEN*GRD];
__device__ __half d_Wh[4*65536];
__device__ __half d_Akv[B_*KVLEN*DIMV];
__device__ __half d_Aq[B_*QLEN*DIMV];
__device__ __half d_w2hi[2*8*512];
__device__ __half d_w2lo[2*8*512];
__device__ __half d_mskh[B_*KVLEN];            // -100*log2e*mask (f16)
__device__ __half d_poh[16*NQT*NSPL*64*32];    // partial O (normalized, f16)
__device__ float  d_pm[16*NQT*NSPL*64];        // partial m
__device__ float  d_pl[16*NQT*NSPL*64];        // partial l
__device__ int    d_cnt[16*NQT];               // arrival counters (zero-init, reset by merger)

// ---------------- helpers ----------------
__device__ __forceinline__ void ldmx4(uint32_t* r, uint32_t a) {
    asm volatile("ldmatrix.sync.aligned.m8n8.x4.shared.b16 {%0,%1,%2,%3}, [%4];"
                 : "=r"(r[0]), "=r"(r[1]), "=r"(r[2]), "=r"(r[3]) : "r"(a));
}
__device__ __forceinline__ void ldmx2(uint32_t* r, uint32_t a) {
    asm volatile("ldmatrix.sync.aligned.m8n8.x2.shared.b16 {%0,%1}, [%2];"
                 : "=r"(r[0]), "=r"(r[1]) : "r"(a));
}
__device__ __forceinline__ void ldmx2t(uint32_t* r, uint32_t a) {
    asm volatile("ldmatrix.sync.aligned.m8n8.x2.trans.shared.b16 {%0,%1}, [%2];"
                 : "=r"(r[0]), "=r"(r[1]) : "r"(a));
}
__device__ __forceinline__ void mma16816(float* c, const uint32_t* a, const uint32_t* b) {
    asm volatile("mma.sync.aligned.m16n8k16.row.col.f32.f16.f16.f32 "
                 "{%0,%1,%2,%3}, {%4,%5,%6,%7}, {%8,%9}, {%0,%1,%2,%3};"
                 : "+f"(c[0]), "+f"(c[1]), "+f"(c[2]), "+f"(c[3])
                 : "r"(a[0]), "r"(a[1]), "r"(a[2]), "r"(a[3]), "r"(b[0]), "r"(b[1]));
}
__device__ __forceinline__ uint32_t smem_u32(const void* p) {
    return (uint32_t)__cvta_generic_to_shared(p);
}
__device__ __forceinline__ uint32_t packh2(float a, float b) {
    __half2 h = __floats2half2_rn(a, b);
    return *(uint32_t*)&h;
}
__device__ __forceinline__ float ex2(float x) {
    float y;
    asm("ex2.approx.ftz.f32 %0, %1;" : "=f"(y) : "f"(x));
    return y;
}
#define CP16(dst, src) asm volatile("cp.async.cg.shared.global [%0], [%1], 16;" :: "r"(dst), "l"(src) : "memory")
#define CP_COMMIT() asm volatile("cp.async.commit_group;" ::: "memory")
#define CP_WAIT0() asm volatile("cp.async.wait_group 0;" ::: "memory")

// ---------------- one-shot convert ----------------
__global__ void convert_all(const float* __restrict__ qw, const float* __restrict__ kw,
                            const float* __restrict__ vw, const float* __restrict__ ow,
                            const float* __restrict__ kvst, const float* __restrict__ hidden,
                            const float* __restrict__ m1w2, const float* __restrict__ m2w2,
                            const int* __restrict__ amask)
{
    unsigned u = blockIdx.x * 256 + threadIdx.x;
    if (u < 705024u) {
        const float* src; __half* dst; unsigned off;
        if      (u <  16384) { src = qw;     dst = d_Wh;          off = u; }
        else if (u <  32768) { src = kw;     dst = d_Wh + 65536;  off = u - 16384; }
        else if (u <  49152) { src = vw;     dst = d_Wh + 131072; off = u - 32768; }
        else if (u <  65536) { src = ow;     dst = d_Wh + 196608; off = u - 49152; }
        else if (u < 589824) { src = kvst;   dst = d_Akv;         off = u - 65536; }
        else                 { src = hidden; dst = d_Aq;          off = u - 589824; }
        float4 f = ((const float4*)src)[off];
        uint2 o; o.x = packh2(f.x, f.y); o.y = packh2(f.z, f.w);
        ((uint2*)dst)[off] = o;
    } else if (u < 707072u) {
        unsigned off = u - 705024u;
        int axis = off >> 10;
        unsigned o2 = off & 1023;
        const float* src = axis ? m2w2 : m1w2;
        float4 f = ((const float4*)src)[o2];
        __half hx = __float2half_rn(f.x), hy = __float2half_rn(f.y);
        __half hz = __float2half_rn(f.z), hw = __float2half_rn(f.w);
        uint2 hiu, lou;
        {
            __half2 a; a.x = hx; a.y = hy; hiu.x = *(uint32_t*)&a;
            __half2 b; b.x = hz; b.y = hw; hiu.y = *(uint32_t*)&b;
        }
        lou.x = packh2(f.x - __half2float(hx), f.y - __half2float(hy));
        lou.y = packh2(f.z - __half2float(hz), f.w - __half2float(hw));
        ((uint2*)(d_w2hi + axis * 4096))[o2] = hiu;
        ((uint2*)(d_w2lo + axis * 4096))[o2] = lou;
    } else if (u < 709120u) {
        unsigned off = u - 707072u;
        int4 m = ((const int4*)amask)[off];
        uint2 o;
        o.x = packh2(-100.0f * L2E * m.x, -100.0f * L2E * m.y);
        o.y = packh2(-100.0f * L2E * m.z, -100.0f * L2E * m.w);
        ((uint2*)d_mskh)[off] = o;
    } else {
        unsigned off = u - 709120u;
        if (off < 16 * NQT) d_cnt[off] = 0;
    }
}

// ---------------- HMMA GEMM core: 128x32 tile, optional dual weights ----------------
__device__ __forceinline__ void gemm_core(char* smem, int bm, int bn,
    const __half* __restrict__ Ah,
    const __half* __restrict__ W1, const float* __restrict__ b1v, void* C1,
    const __half* __restrict__ W2, const float* __restrict__ b2v, void* C2,
    int M, int rpb, float scale)
{
    __half* As  = (__half*)smem;
    __half* Ws1 = (__half*)(smem + 10240);
    __half* Ws2 = (__half*)(smem + 12800);

    const int tid = threadIdx.x;
    const int lane = tid & 31;
    const int wid = tid >> 5;
    const bool dual = (W2 != nullptr);

    const int arow = tid >> 1, aseg = (tid & 1) * 16;
    const int wrow = tid >> 3, wseg = (tid & 7) * 4;

    float c1[4][4], c2[4][4];
#pragma unroll
    for (int j = 0; j < 4; j++) {
        c1[j][0] = c1[j][1] = c1[j][2] = c1[j][3] = 0.f;
        c2[j][0] = c2[j][1] = c2[j][2] = c2[j][3] = 0.f;
    }

    const uint32_t AsB = smem_u32(As);
    const uint32_t W1B = smem_u32(Ws1);
    const uint32_t W2B = smem_u32(Ws2);

    uint4 pa0 = make_uint4(0,0,0,0), pa1 = pa0;
    uint2 pw1, pw2 = make_uint2(0,0);
    if (bm + arow < M) {
        const uint4* ap = (const uint4*)&Ah[(size_t)(bm + arow) * 256 + aseg];
        pa0 = ap[0]; pa1 = ap[1];
    }
    pw1 = *(const uint2*)&W1[(size_t)(bn + wrow) * 256 + wseg];
    if (dual) pw2 = *(const uint2*)&W2[(size_t)(bn + wrow) * 256 + wseg];

#pragma unroll 1
    for (int kit = 0; kit < 8; kit++) {
        *(uint4*)&As[arow * 40 + aseg]     = pa0;
        *(uint4*)&As[arow * 40 + aseg + 8] = pa1;
        *(uint2*)&Ws1[wrow * 40 + wseg]    = pw1;
        if (dual) *(uint2*)&Ws2[wrow * 40 + wseg] = pw2;
        __syncthreads();

        if (kit < 7) {
            int k0 = (kit + 1) * 32;
            pa0 = make_uint4(0,0,0,0); pa1 = pa0;
            if (bm + arow < M) {
                const uint4* ap = (const uint4*)&Ah[(size_t)(bm + arow) * 256 + k0 + aseg];
                pa0 = ap[0]; pa1 = ap[1];
            }
            pw1 = *(const uint2*)&W1[(size_t)(bn + wrow) * 256 + k0 + wseg];
            if (dual) pw2 = *(const uint2*)&W2[(size_t)(bn + wrow) * 256 + k0 + wseg];
        }

        uint32_t a0[4], a1[4];
        uint32_t aa = AsB + (uint32_t)((wid * 16 + (lane & 15)) * 40 + ((lane >> 4) * 8)) * 2;
        ldmx4(a0, aa);
        ldmx4(a1, aa + 32);
#pragma unroll
        for (int j = 0; j < 4; j++) {
            uint32_t woff = (uint32_t)((j * 8 + (lane & 7)) * 40 + ((lane >> 3) & 1) * 8) * 2;
            uint32_t b0[2], b1[2];
            ldmx2(b0, W1B + woff);
            ldmx2(b1, W1B + woff + 32);
            mma16816(c1[j], a0, b0);
            mma16816(c1[j], a1, b1);
            if (dual) {
                ldmx2(b0, W2B + woff);
                ldmx2(b1, W2B + woff + 32);
                mma16816(c2[j], a0, b0);
                mma16816(c2[j], a1, b1);
            }
        }
        __syncthreads();
    }

    const int r0 = bm + wid * 16 + (lane >> 2);
    const int cb = 2 * (lane & 3);
    {
        __half* Ca = (__half*)C1;
        __half* Cb = (__half*)C2;
        int ba = r0 / rpb, ra = r0 - ba * rpb;
        int bb = (r0 + 8) / rpb, rb = (r0 + 8) - bb * rpb;
#pragma unroll
        for (int j = 0; j < 4; j++) {
            int col = bn + j * 8 + cb;
            int head = col >> 5, d = col & 31;
            float x0 = b1v[col], x1 = b1v[col + 1];
            if (r0 < M) {
                *(uint32_t*)&Ca[((size_t)((ba * NH + head) * rpb + ra)) * HD + d] =
                    packh2((c1[j][0] + x0) * scale, (c1[j][1] + x1) * scale);
            }
            if (r0 + 8 < M) {
                *(uint32_t*)&Ca[((size_t)((bb * NH + head) * rpb + rb)) * HD + d] =
                    packh2((c1[j][2] + x0) * scale, (c1[j][3] + x1) * scale);
            }
            if (dual) {
                float y0 = b2v[col], y1 = b2v[col + 1];
                if (r0 < M) {
                    *(uint32_t*)&Cb[((size_t)((ba * NH + head) * rpb + ra)) * HD + d] =
                        packh2((c2[j][0] + y0) * scale, (c2[j][1] + y1) * scale);
                }
                if (r0 + 8 < M) {
                    *(uint32_t*)&Cb[((size_t)((bb * NH + head) * rpb + rb)) * HD + d] =
                        packh2((c2[j][2] + y0) * scale, (c2[j][3] + y1) * scale);
                }
            }
        }
    }
}

// ---------------- RPE core ----------------
#define MKFRAG(px, hi0, lo0, hi1, lo1) { \
    float h0 = fmaxf(v0.x - v0.y * (px), 0.f); \
    float h1 = fmaxf(v0.z - v0.w * (px), 0.f); \
    float h2 = fmaxf(v1.x - v1.y * (px), 0.f); \
    float h3 = fmaxf(v1.z - v1.w * (px), 0.f); \
    __half2 t0 = __floats2half2_rn(h0, h1); float2 g0 = __half22float2(t0); \
    __half2 u0 = __floats2half2_rn(h0 - g0.x, h1 - g0.y); \
    __half2 t1 = __floats2half2_rn(h2, h3); float2 g1 = __half22float2(t1); \
    __half2 u1 = __floats2half2_rn(h2 - g1.x, h3 - g1.y); \
    hi0 = *(uint32_t*)&t0; lo0 = *(uint32_t*)&u0; \
    hi1 = *(uint32_t*)&t1; lo1 = *(uint32_t*)&u1; }

__device__ __forceinline__ void rpe_core(char* smem, int q0, int b, int axis,
    const float* __restrict__ refpts,
    const float* __restrict__ w1a, const float* __restrict__ b1a,
    const float* __restrict__ w1b, const float* __restrict__ b1b)
{
    __half* w2hi = (__half*)smem;
    __half* w2lo = (__half*)(smem + 8320);
    float2* as2  = (float2*)(smem + 16640);

    const int tid = threadIdx.x;
    const int lane = tid & 31;
    const int wid = tid >> 5;

    const float* w1  = axis ? w1b : w1a;
    const float* bb1 = axis ? b1b : b1a;
    float* out = axis ? d_rpey : d_rpex;

    const __half* ghi = d_w2hi + axis * 4096;
    const __half* glo = d_w2lo + axis * 4096;
#pragma unroll
    for (int i = tid; i < 2048; i += 256) {
        int h = i >> 8, jj = (i & 255) * 2;
        *(uint32_t*)&w2hi[h * 520 + jj] = *(const uint32_t*)&ghi[h * 512 + jj];
        *(uint32_t*)&w2lo[h * 520 + jj] = *(const uint32_t*)&glo[h * 512 + jj];
    }
#pragma unroll
    for (int i = tid; i < 4 * 512; i += 256) {
        int qi = i >> 9, j = i & 511;
        const float* rp = refpts + ((size_t)b * QLEN + q0 + qi) * 4;
        float cc = rp[axis], ss = rp[2 + axis];
        float lo = (cc - 0.5f * ss) * 1024.f, hi = (cc + 0.5f * ss) * 1024.f;
        float wx = w1[j * 2], wy = w1[j * 2 + 1];
        as2[qi * 512 + j] = make_float2(wx * lo + wy * hi + bb1[j], wx + wy);
    }
    __syncthreads();

    const int qi = wid >> 1;
    const int mt = wid & 1;
    const int q = q0 + qi;
    const int r = lane >> 2;
    const int c0 = 2 * (lane & 3);
    const float pxA = (mt * 16 + r + 0.5f) * 16.f;
    const float pxB = pxA + 128.f;
    const float pxC = pxA + 512.f;
    const float pxD = pxA + 640.f;

    const uint32_t WhiB = smem_u32(w2hi);
    const uint32_t WloB = smem_u32(w2lo);
    const float2* asq = as2 + qi * 512;

    float cA[4] = {0.f, 0.f, 0.f, 0.f};
    float cB[4] = {0.f, 0.f, 0.f, 0.f};

#pragma unroll 4
    for (int kk = 0; kk < 32; kk++) {
        int j0 = kk * 16 + c0;
        float4 v0 = *(const float4*)&asq[j0];
        float4 v1 = *(const float4*)&asq[j0 + 8];

        uint32_t ahiA[4], aloA[4], ahiB[4], aloB[4];
        MKFRAG(pxA, ahiA[0], aloA[0], ahiA[2], aloA[2]);
        MKFRAG(pxB, ahiA[1], aloA[1], ahiA[3], aloA[3]);
        MKFRAG(pxC, ahiB[0], aloB[0], ahiB[2], aloB[2]);
        MKFRAG(pxD, ahiB[1], aloB[1], ahiB[3], aloB[3]);

        uint32_t woff = (uint32_t)((lane & 7) * 520 + kk * 16 + ((lane >> 3) & 1) * 8) * 2;
        uint32_t bhi[2], blo[2];
        ldmx2(bhi, WhiB + woff);
        ldmx2(blo, WloB + woff);
        mma16816(cA, ahiA, bhi);
        mma16816(cA, aloA, bhi);
        mma16816(cA, ahiA, blo);
        mma16816(cB, ahiB, bhi);
        mma16816(cB, aloB, bhi);
        mma16816(cB, ahiB, blo);
    }

    {
        int p0 = mt * 16 + r;
        size_t hstride = (size_t)QLEN * GRD;
        size_t base = ((size_t)(b * NH + c0) * QLEN + q) * GRD;
        out[base + p0]               = cA[0] * L2E;
        out[base + hstride + p0]     = cA[1] * L2E;
        out[base + p0 + 8]           = cA[2] * L2E;
        out[base + hstride + p0 + 8] = cA[3] * L2E;
        out[base + p0 + 32]               = cB[0] * L2E;
        out[base + hstride + p0 + 32]     = cB[1] * L2E;
        out[base + p0 + 40]               = cB[2] * L2E;
        out[base + hstride + p0 + 40]     = cB[3] * L2E;
    }
}

// ---------------- fat mid-kernel ----------------
#define FAT_SMEM 33024
__global__ void __launch_bounds__(256, 4) fat_mid(
    const float* __restrict__ refpts,
    const float* __restrict__ w1a, const float* __restrict__ b1a,
    const float* __restrict__ w1b, const float* __restrict__ b1b,
    const float* __restrict__ qb, const float* __restrict__ kb,
    const float* __restrict__ vb, float qs2)
{
    extern __shared__ char smem[];
    int bx = blockIdx.x;
    if (bx < 900) {
        int axis = bx / 450;
        int rem = bx - axis * 450;
        int b = rem / 225;
        int q0 = (rem % 225) * 4;
        rpe_core(smem, q0, b, axis, refpts, w1a, b1a, w1b, b1b);
    } else if (bx < 1412) {
        int i = bx - 900;
        gemm_core(smem, (i & 63) * 128, (i >> 6) * 32,
                  d_Akv, d_Wh + 65536, kb, d_Kh, d_Wh + 131072, vb, d_Vh,
                  B_ * KVLEN, KVLEN, 1.0f);
    } else {
        int i = bx - 1412;
        gemm_core(smem, (i % 15) * 128, (i / 15) * 32,
                  d_Aq, d_Wh, qb, d_Qh, nullptr, nullptr, nullptr,
                  B_ * QLEN, QLEN, qs2);
    }
}

// ---------------- O projection: 64x32 tile, 128 threads ----------
__global__ void __launch_bounds__(128) gemm_o64(const float* __restrict__ ob, float* __restrict__ out)
{
    __shared__ __half As[64 * 40];
    __shared__ __half Ws[32 * 40];

    const int tid = threadIdx.x;
    const int lane = tid & 31;
    const int wid = tid >> 5;
    const int bm = blockIdx.x * 64;
    const int bn = blockIdx.y * 32;
    const int M = B_ * QLEN;
    const __half* W1 = d_Wh + 196608;

    const int arow = tid >> 1, aseg = (tid & 1) * 16;
    const int wrow = tid >> 2, wseg = (tid & 3) * 8;

    float c1[4][4];
#pragma unroll
    for (int j = 0; j < 4; j++) { c1[j][0] = c1[j][1] = c1[j][2] = c1[j][3] = 0.f; }

    const uint32_t AsB = smem_u32(As);
    const uint32_t WsB = smem_u32(Ws);

    uint4 pa0 = make_uint4(0,0,0,0), pa1 = pa0;
    uint4 pw;
    if (bm + arow < M) {
        const uint4* ap = (const uint4*)&d_ctxh[(size_t)(bm + arow) * 256 + aseg];
        pa0 = ap[0]; pa1 = ap[1];
    }
    pw = *(const uint4*)&W1[(size_t)(bn + wrow) * 256 + wseg];

#pragma unroll 1
    for (int kit = 0; kit < 8; kit++) {
        *(uint4*)&As[arow * 40 + aseg]     = pa0;
        *(uint4*)&As[arow * 40 + aseg + 8] = pa1;
        *(uint4*)&Ws[wrow * 40 + wseg]     = pw;
        __syncthreads();

        if (kit < 7) {
            int k0 = (kit + 1) * 32;
            pa0 = make_uint4(0,0,0,0); pa1 = pa0;
            if (bm + arow < M) {
                const uint4* ap = (const uint4*)&d_ctxh[(size_t)(bm + arow) * 256 + k0 + aseg];
                pa0 = ap[0]; pa1 = ap[1];
            }
            pw = *(const uint4*)&W1[(size_t)(bn + wrow) * 256 + k0 + wseg];
        }

        uint32_t a0[4], a1[4];
        uint32_t aa = AsB + (uint32_t)((wid * 16 + (lane & 15)) * 40 + ((lane >> 4) * 8)) * 2;
        ldmx4(a0, aa);
        ldmx4(a1, aa + 32);
#pragma unroll
        for (int j = 0; j < 4; j++) {
            uint32_t woff = (uint32_t)((j * 8 + (lane & 7)) * 40 + ((lane >> 3) & 1) * 8) * 2;
            uint32_t b0[2], b1[2];
            ldmx2(b0, WsB + woff);
            ldmx2(b1, WsB + woff + 32);
            mma16816(c1[j], a0, b0);
            mma16816(c1[j], a1, b1);
        }
        __syncthreads();
    }

    const int r0 = bm + wid * 16 + (lane >> 2);
    const int cb = 2 * (lane & 3);
#pragma unroll
    for (int j = 0; j < 4; j++) {
        int col = bn + j * 8 + cb;
        float bb0 = ob[col], bb1 = ob[col + 1];
        if (r0 < M)     *(float2*)&out[(size_t)r0 * 256 + col]       = make_float2(c1[j][0] + bb0, c1[j][1] + bb1);
        if (r0 + 8 < M) *(float2*)&out[(size_t)(r0 + 8) * 256 + col] = make_float2(c1[j][2] + bb0, c1[j][3] + bb1);
    }
}

// ---------------- split-KV HMMA flash attention + fused last-block merge ------
#define PK 40
#define PRY 20
#define QS_OFF  0
#define KS_OFF  5120
#define VS_OFF  15360
#define RY_OFF  25600
#define MK_OFF  30720
#define FLAG_OFF 32764
#define ATTN_SMEM 32768

__global__ void __launch_bounds__(128) attn_split()
{
    extern __shared__ char smem[];
    __half* Qs  = (__half*)(smem + QS_OFF);
    float*  rys = (float*)(smem + RY_OFF);
    __half* mks = (__half*)(smem + MK_OFF);
    int*    flg = (int*)(smem + FLAG_OFF);

    const int tid = threadIdx.x;
    const int lane = tid & 31;
    const int wid = tid >> 5;
    const int qt = blockIdx.x;
    const int bh = blockIdx.y;
    const int kvh = blockIdx.z;
    const int b = bh >> 3;
    const int q0 = qt * 64;
    const int kv0 = kvh * (KVLEN / NSPL);

    const __half* Kb = d_Kh + (size_t)bh * KVLEN * HD + (size_t)kv0 * HD;
    const __half* Vb = d_Vh + (size_t)bh * KVLEN * HD + (size_t)kv0 * HD;

    const int srow = tid >> 1, sseg = (tid & 1) * 16;
    {
        uint32_t kd = smem_u32(smem + KS_OFF) + (uint32_t)(srow * PK + sseg) * 2;
        uint32_t vd = smem_u32(smem + VS_OFF) + (uint32_t)(srow * PK + sseg) * 2;
        const __half* ks = Kb + (size_t)srow * HD + sseg;
        const __half* vs = Vb + (size_t)srow * HD + sseg;
        CP16(kd, ks); CP16(kd + 16, ks + 8);
        CP16(vd, vs); CP16(vd + 16, vs + 8);
        CP_COMMIT();
    }

    if (tid < 128) {
        const uint4* mg = (const uint4*)(d_mskh + b * KVLEN + kv0);
        ((uint4*)mks)[tid] = mg[tid];
    }

    {
        int row = tid >> 1, seg = tid & 1;
        int q = q0 + row;
        uint4 v0 = make_uint4(0, 0, 0, 0), v1 = make_uint4(0, 0, 0, 0);
        if (q < QLEN) {
            const uint4* qp = (const uint4*)(d_Qh + ((size_t)bh * QLEN + q) * HD + seg * 16);
            v0 = qp[0]; v1 = qp[1];
        }
        *(uint4*)(Qs + row * PK + seg * 16)     = v0;
        *(uint4*)(Qs + row * PK + seg * 16 + 8) = v1;
    }
    {
        int row = tid >> 1, sb = (tid & 1) * 8;
        int q = q0 + row;
        if (q < QLEN) {
            const float4* py = (const float4*)(d_rpey + ((size_t)bh * QLEN + q) * GRD + kvh * 16 + sb);
            *(float4*)(rys + row * PRY + sb)     = py[0];
            *(float4*)(rys + row * PRY + sb + 4) = py[1];
        } else {
            float4 z = make_float4(0.f, 0.f, 0.f, 0.f);
            *(float4*)(rys + row * PRY + sb)     = z;
            *(float4*)(rys + row * PRY + sb + 4) = z;
        }
    }
    __syncthreads();

    uint32_t aQ[2][4];
    {
        uint32_t base = smem_u32(Qs);
        int m = wid * 16 + (lane & 15);
        uint32_t a0 = base + (uint32_t)(m * PK + ((lane >> 4) * 8)) * 2;
        ldmx4(aQ[0], a0);
        ldmx4(aQ[1], a0 + 32);
    }

    const int r0 = wid * 16 + (lane >> 2);
    const int cb = 2 * (lane & 3);

    float2 rxa[8], rxb[8];
    {
        int qa = q0 + r0, qb2 = qa + 8;
        const float* rxg = d_rpex + (size_t)bh * QLEN * GRD;
        float2 z = make_float2(0.f, 0.f);
#pragma unroll
        for (int j = 0; j < 8; j++) {
            int n = j * 8 + cb;
            rxa[j] = (qa  < QLEN) ? *(const float2*)&rxg[(size_t)qa  * GRD + n] : z;
            rxb[j] = (qb2 < QLEN) ? *(const float2*)&rxg[(size_t)qb2 * GRD + n] : z;
        }
    }

    float oc[4][4];
#pragma unroll
    for (int i = 0; i < 4; i++)
#pragma unroll
        for (int j = 0; j < 4; j++) oc[i][j] = 0.f;
    float m_run0 = -1e30f, m_run1 = -1e30f, l_run0 = 0.f, l_run1 = 0.f;

    const int NT = KVLEN / NSPL / 64;  // 16 tiles
    for (int t = 0; t < NT; t++) {
        CP_WAIT0();
        __syncthreads();
        if (t + 1 < NT) {
            int buf = (t + 1) & 1;
            uint32_t kd = smem_u32(smem + KS_OFF + buf * 5120) + (uint32_t)(srow * PK + sseg) * 2;
            uint32_t vd = smem_u32(smem + VS_OFF + buf * 5120) + (uint32_t)(srow * PK + sseg) * 2;
            const __half* ks = Kb + (size_t)((t + 1) * 64 + srow) * HD + sseg;
            const __half* vs = Vb + (size_t)((t + 1) * 64 + srow) * HD + sseg;
            CP16(kd, ks); CP16(kd + 16, ks + 8);
            CP16(vd, vs); CP16(vd + 16, vs + 8);
            CP_COMMIT();
        }

        const uint32_t KsB = smem_u32(smem + KS_OFF + (t & 1) * 5120);
        const uint32_t VsB = smem_u32(smem + VS_OFF + (t & 1) * 5120);

        float sc[8][4];
#pragma unroll
        for (int j = 0; j < 8; j++) {
            sc[j][0] = sc[j][1] = sc[j][2] = sc[j][3] = 0.f;
            uint32_t addr = KsB + (uint32_t)((j * 8 + (lane & 7)) * PK + ((lane >> 3) & 1) * 8) * 2;
            uint32_t bk0[2], bk1[2];
            ldmx2(bk0, addr);
            ldmx2(bk1, addr + 32);
            mma16816(sc[j], aQ[0], bk0);
            mma16816(sc[j], aQ[1], bk1);
        }

        float mx0 = -1e30f, mx1 = -1e30f;
#pragma unroll
        for (int j = 0; j < 8; j++) {
            int n = j * 8 + cb;
            float2 mk = __half22float2(*(__half2*)(mks + t * 64 + n));
            sc[j][0] += rxa[j].x + mk.x;
            sc[j][1] += rxa[j].y + mk.y;
            sc[j][2] += rxb[j].x + mk.x;
            sc[j][3] += rxb[j].y + mk.y;
            mx0 = fmaxf(mx0, fmaxf(sc[j][0], sc[j][1]));
            mx1 = fmaxf(mx1, fmaxf(sc[j][2], sc[j][3]));
        }
        mx0 = fmaxf(mx0, __shfl_xor_sync(0xffffffffu, mx0, 1));
        mx0 = fmaxf(mx0, __shfl_xor_sync(0xffffffffu, mx0, 2));
        mx1 = fmaxf(mx1, __shfl_xor_sync(0xffffffffu, mx1, 1));
        mx1 = fmaxf(mx1, __shfl_xor_sync(0xffffffffu, mx1, 2));

        float ry0 = rys[r0 * PRY + t];
        float ry1 = rys[(r0 + 8) * PRY + t];
        float mn0 = fmaxf(m_run0, mx0 + ry0), mn1 = fmaxf(m_run1, mx1 + ry1);
        float base0 = mn0 - ry0, base1 = mn1 - ry1;
        float f0 = ex2(m_run0 - mn0), f1 = ex2(m_run1 - mn1);
        m_run0 = mn0; m_run1 = mn1;

        float la0 = 0.f, la1 = 0.f;
        uint32_t pa[4][4];
#pragma unroll
        for (int j = 0; j < 8; j++) {
            float p0 = ex2(sc[j][0] - base0);
            float p1 = ex2(sc[j][1] - base0);
            float p2 = ex2(sc[j][2] - base1);
            float p3 = ex2(sc[j][3] - base1);
            la0 += p0 + p1; la1 += p2 + p3;
            int kt = j >> 1, hi = j & 1;
            pa[kt][2 * hi]     = packh2(p0, p1);
            pa[kt][2 * hi + 1] = packh2(p2, p3);
        }
        l_run0 = l_run0 * f0 + la0;
        l_run1 = l_run1 * f1 + la1;

#pragma unroll
        for (int no = 0; no < 4; no++) {
            oc[no][0] *= f0; oc[no][1] *= f0;
            oc[no][2] *= f1; oc[no][3] *= f1;
        }

#pragma unroll
        for (int kt = 0; kt < 4; kt++) {
            uint32_t addr = VsB + (uint32_t)((kt * 16 + (lane & 15)) * PK) * 2;
#pragma unroll
            for (int no = 0; no < 4; no++) {
                uint32_t bv[2];
                ldmx2t(bv, addr + (uint32_t)(no * 8) * 2);
                mma16816(oc[no], pa[kt], bv);
            }
        }
    }

    // final quad reduction of l
    l_run0 += __shfl_xor_sync(0xffffffffu, l_run0, 1);
    l_run0 += __shfl_xor_sync(0xffffffffu, l_run0, 2);
    l_run1 += __shfl_xor_sync(0xffffffffu, l_run1, 1);
    l_run1 += __shfl_xor_sync(0xffffffffu, l_run1, 2);

    // write partials (normalized, f16)
    const int grp = bh * NQT + qt;
    {
        int cta = grp * NSPL + kvh;
        __half* po = d_poh + (size_t)cta * 2048;
        float inv0 = 1.0f / l_run0;
        float inv1 = 1.0f / l_run1;
#pragma unroll
        for (int no = 0; no < 4; no++) {
            int d = no * 8 + cb;
            *(uint32_t*)&po[r0 * 32 + d]       = packh2(oc[no][0] * inv0, oc[no][1] * inv0);
            *(uint32_t*)&po[(r0 + 8) * 32 + d] = packh2(oc[no][2] * inv1, oc[no][3] * inv1);
        }
        if ((lane & 3) == 0) {
            d_pm[cta * 64 + r0]     = m_run0;
            d_pm[cta * 64 + r0 + 8] = m_run1;
            d_pl[cta * 64 + r0]     = l_run0;
            d_pl[cta * 64 + r0 + 8] = l_run1;
        }
    }

    // last-block-done merge
    __threadfence();
    __syncthreads();
    if (tid == 0) {
        int old = atomicAdd(&d_cnt[grp], 1);
        *flg = (old == NSPL - 1);
    }
    __syncthreads();
    if (!*flg) return;

    {
        const int ql = tid >> 1;            // 0..63
        const int dh = (tid & 1) * 16;      // half offset within 32-dim row
        const int q = q0 + ql;
        const int c0 = grp * NSPL;
        if (q < QLEN) {
            float ms[NSPL], ls[NSPL];
            float m = -1e30f;
#pragma unroll
            for (int s = 0; s < NSPL; s++) {
                ms[s] = d_pm[(c0 + s) * 64 + ql];
                ls[s] = d_pl[(c0 + s) * 64 + ql];
                m = fmaxf(m, ms[s]);
            }
            float ws[NSPL], lsum = 0.f;
#pragma unroll
            for (int s = 0; s < NSPL; s++) { ws[s] = ls[s] * ex2(ms[s] - m); lsum += ws[s]; }
            float inv = 1.0f / lsum;

            float acc[16];
#pragma unroll
            for (int i = 0; i < 16; i++) acc[i] = 0.f;
#pragma unroll
            for (int s = 0; s < NSPL; s++) {
                const uint4* o = (const uint4*)(d_poh + (size_t)(c0 + s) * 2048 + ql * 32 + dh);
                uint4 v0 = o[0], v1 = o[1];
                float f = ws[s] * inv;
                const uint32_t* va = (const uint32_t*)&v0;
#pragma unroll
                for (int u = 0; u < 4; u++) {
                    float2 hv = __half22float2(*(__half2*)&va[u]);
                    acc[u * 2]     += hv.x * f;
                    acc[u * 2 + 1] += hv.y * f;
                }
                const uint32_t* vb = (const uint32_t*)&v1;
#pragma unroll
                for (int u = 0; u < 4; u++) {
                    float2 hv = __half22float2(*(__half2*)&vb[u]);
                    acc[8 + u * 2]     += hv.x * f;
                    acc[8 + u * 2 + 1] += hv.y * f;
                }
            }
            uint4 w0;
            w0.x = packh2(acc[0], acc[1]);   w0.y = packh2(acc[2], acc[3]);
            w0.z = packh2(acc[4], acc[5]);   w0.w = packh2(acc[6], acc[7]);
            uint4 w1;
            w1.x = packh2(acc[8], acc[9]);   w1.y = packh2(acc[10], acc[11]);
            w1.z = packh2(acc[12], acc[13]); w1.w = packh2(acc[14], acc[15]);
            uint4* dst = (uint4*)(d_ctxh + ((size_t)b * QLEN + q) * DIMV + (bh & 7) * HD + dh);
            dst[0] = w0;
            if (dh == 0) ((uint4*)(d_ctxh + ((size_t)b * QLEN + q) * DIMV + (bh & 7) * HD))[1] = w1;
            else         dst[1] = w1;
        }
        if (tid == 0) d_cnt[grp] = 0;   // reset for next graph replay
    }
}

// ---------------- launch ----------------
extern "C" void kernel_launch(void* const* d_in, const int* in_sizes, int n_in,
                              void* d_out, int out_size)
{
    const float* hidden = (const float*)d_in[0];
    const float* refpts = (const float*)d_in[1];
    const float* kvst   = (const float*)d_in[2];
    const int*   amask  = (const int*)d_in[4];
    const float* m1w1 = (const float*)d_in[5];
    const float* m1b1 = (const float*)d_in[6];
    const float* m1w2 = (const float*)d_in[7];
    const float* m2w1 = (const float*)d_in[8];
    const float* m2b1 = (const float*)d_in[9];
    const float* m2w2 = (const float*)d_in[10];
    const float* qw = (const float*)d_in[11];
    const float* qb = (const float*)d_in[12];
    const float* kw = (const float*)d_in[13];
    const float* kb = (const float*)d_in[14];
    const float* vw = (const float*)d_in[15];
    const float* vb = (const float*)d_in[16];
    const float* ow = (const float*)d_in[17];
    const float* ob = (const float*)d_in[18];
    float* out = (float*)d_out;

    cudaFuncSetAttribute(attn_split, cudaFuncAttributeMaxDynamicSharedMemorySize, ATTN_SMEM);

    const float qs2 = 0.17677669529663687f * L2E;

    convert_all<<<2771, 256>>>(qw, kw, vw, ow, kvst, hidden, m1w2, m2w2, amask);
    fat_mid<<<1532, 256, FAT_SMEM>>>(refpts, m1w1, m1b1, m2w1, m2b1, qb, kb, vb, qs2);
    attn_split<<<dim3(NQT, B_ * NH, NSPL), 128, ATTN_SMEM>>>();
    gemm_o64<<<dim3(29, 8), 128>>>(ob, out);
}

// round 17
// speedup vs baseline: 1.0066x; 1.0066x over previous
#include <cuda_runtime.h>
#include <cuda_fp16.h>
#include <cstdint>

#define B_    2
#define QLEN  900
#define DIMV  256
#define NH    8
#define HD    32
#define KVLEN 4096
#define GRD   64
#define RPEH  512
#define L2E   1.4426950408889634f
#define NQT   15          // q tiles of 64
#define NSPL  8           // kv splits

// ---------------- scratch ----------------
__device__ __half d_Qh[B_*NH*QLEN*HD];
__device__ __half d_Kh[B_*NH*KVLEN*HD];
__device__ __half d_Vh[B_*NH*KVLEN*HD];
__device__ __half d_ctxh[B_*QLEN*DIMV];
__device__ float  d_rpex[B_*NH*QLEN*GRD];
__device__ float  d_rpey[B_*NH*QLEN*GRD];
__device__ __half d_Wh[4*65536];
__device__ __half d_Akv[B_*KVLEN*DIMV];
__device__ __half d_Aq[B_*QLEN*DIMV];
__device__ __half d_w2hi[2*8*512];
__device__ __half d_w2lo[2*8*512];
__device__ __half d_mskh[B_*KVLEN];            // -100*log2e*mask (f16)
__device__ __half d_poh[16*NQT*NSPL*64*32];    // partial O (normalized, f16)
__device__ float  d_pm[16*NQT*NSPL*64];        // partial m
__device__ float  d_pl[16*NQT*NSPL*64];        // partial l

// ---------------- helpers ----------------
__device__ __forceinline__ void ldmx4(uint32_t* r, uint32_t a) {
    asm volatile("ldmatrix.sync.aligned.m8n8.x4.shared.b16 {%0,%1,%2,%3}, [%4];"
                 : "=r"(r[0]), "=r"(r[1]), "=r"(r[2]), "=r"(r[3]) : "r"(a));
}
__device__ __forceinline__ void ldmx2(uint32_t* r, uint32_t a) {
    asm volatile("ldmatrix.sync.aligned.m8n8.x2.shared.b16 {%0,%1}, [%2];"
                 : "=r"(r[0]), "=r"(r[1]) : "r"(a));
}
__device__ __forceinline__ void ldmx2t(uint32_t* r, uint32_t a) {
    asm volatile("ldmatrix.sync.aligned.m8n8.x2.trans.shared.b16 {%0,%1}, [%2];"
                 : "=r"(r[0]), "=r"(r[1]) : "r"(a));
}
__device__ __forceinline__ void mma16816(float* c, const uint32_t* a, const uint32_t* b) {
    asm volatile("mma.sync.aligned.m16n8k16.row.col.f32.f16.f16.f32 "
                 "{%0,%1,%2,%3}, {%4,%5,%6,%7}, {%8,%9}, {%0,%1,%2,%3};"
                 : "+f"(c[0]), "+f"(c[1]), "+f"(c[2]), "+f"(c[3])
                 : "r"(a[0]), "r"(a[1]), "r"(a[2]), "r"(a[3]), "r"(b[0]), "r"(b[1]));
}
__device__ __forceinline__ uint32_t smem_u32(const void* p) {
    return (uint32_t)__cvta_generic_to_shared(p);
}
__device__ __forceinline__ uint32_t packh2(float a, float b) {
    __half2 h = __floats2half2_rn(a, b);
    return *(uint32_t*)&h;
}
__device__ __forceinline__ float ex2(float x) {
    float y;
    asm("ex2.approx.ftz.f32 %0, %1;" : "=f"(y) : "f"(x));
    return y;
}
#define CP16(dst, src) asm volatile("cp.async.cg.shared.global [%0], [%1], 16;" :: "r"(dst), "l"(src) : "memory")
#define CP_COMMIT() asm volatile("cp.async.commit_group;" ::: "memory")
#define CP_WAIT0() asm volatile("cp.async.wait_group 0;" ::: "memory")

// ---------------- one-shot convert (+ zero out for split-K atomics) ----------------
__global__ void convert_all(const float* __restrict__ qw, const float* __restrict__ kw,
                            const float* __restrict__ vw, const float* __restrict__ ow,
                            const float* __restrict__ kvst, const float* __restrict__ hidden,
                            const float* __restrict__ m1w2, const float* __restrict__ m2w2,
                            const int* __restrict__ amask, float* __restrict__ out)
{
    unsigned u = blockIdx.x * 256 + threadIdx.x;
    if (u < 705024u) {
        const float* src; __half* dst; unsigned off;
        if      (u <  16384) { src = qw;     dst = d_Wh;          off = u; }
        else if (u <  32768) { src = kw;     dst = d_Wh + 65536;  off = u - 16384; }
        else if (u <  49152) { src = vw;     dst = d_Wh + 131072; off = u - 32768; }
        else if (u <  65536) { src = ow;     dst = d_Wh + 196608; off = u - 49152; }
        else if (u < 589824) { src = kvst;   dst = d_Akv;         off = u - 65536; }
        else                 { src = hidden; dst = d_Aq;          off = u - 589824; }
        float4 f = ((const float4*)src)[off];
        uint2 o; o.x = packh2(f.x, f.y); o.y = packh2(f.z, f.w);
        ((uint2*)dst)[off] = o;
    } else if (u < 707072u) {
        unsigned off = u - 705024u;
        int axis = off >> 10;
        unsigned o2 = off & 1023;
        const float* src = axis ? m2w2 : m1w2;
        float4 f = ((const float4*)src)[o2];
        __half hx = __float2half_rn(f.x), hy = __float2half_rn(f.y);
        __half hz = __float2half_rn(f.z), hw = __float2half_rn(f.w);
        uint2 hiu, lou;
        {
            __half2 a; a.x = hx; a.y = hy; hiu.x = *(uint32_t*)&a;
            __half2 b; b.x = hz; b.y = hw; hiu.y = *(uint32_t*)&b;
        }
        lou.x = packh2(f.x - __half2float(hx), f.y - __half2float(hy));
        lou.y = packh2(f.z - __half2float(hz), f.w - __half2float(hw));
        ((uint2*)(d_w2hi + axis * 4096))[o2] = hiu;
        ((uint2*)(d_w2lo + axis * 4096))[o2] = lou;
    } else if (u < 709120u) {
        unsigned off = u - 707072u;
        int4 m = ((const int4*)amask)[off];
        uint2 o;
        o.x = packh2(-100.0f * L2E * m.x, -100.0f * L2E * m.y);
        o.y = packh2(-100.0f * L2E * m.z, -100.0f * L2E * m.w);
        ((uint2*)d_mskh)[off] = o;
    } else if (u < 824320u) {
        unsigned off = u - 709120u;   // 115200 float4 units = 460800 floats
        ((float4*)out)[off] = make_float4(0.f, 0.f, 0.f, 0.f);
    }
}

// ---------------- HMMA GEMM core: 128x32 tile, optional dual weights ----------------
__device__ __forceinline__ void gemm_core(char* smem, int bm, int bn,
    const __half* __restrict__ Ah,
    const __half* __restrict__ W1, const float* __restrict__ b1v, void* C1,
    const __half* __restrict__ W2, const float* __restrict__ b2v, void* C2,
    int M, int rpb, float scale)
{
    __half* As  = (__half*)smem;
    __half* Ws1 = (__half*)(smem + 10240);
    __half* Ws2 = (__half*)(smem + 12800);

    const int tid = threadIdx.x;
    const int lane = tid & 31;
    const int wid = tid >> 5;
    const bool dual = (W2 != nullptr);

    const int arow = tid >> 1, aseg = (tid & 1) * 16;
    const int wrow = tid >> 3, wseg = (tid & 7) * 4;

    float c1[4][4], c2[4][4];
#pragma unroll
    for (int j = 0; j < 4; j++) {
        c1[j][0] = c1[j][1] = c1[j][2] = c1[j][3] = 0.f;
        c2[j][0] = c2[j][1] = c2[j][2] = c2[j][3] = 0.f;
    }

    const uint32_t AsB = smem_u32(As);
    const uint32_t W1B = smem_u32(Ws1);
    const uint32_t W2B = smem_u32(Ws2);

    uint4 pa0 = make_uint4(0,0,0,0), pa1 = pa0;
    uint2 pw1, pw2 = make_uint2(0,0);
    if (bm + arow < M) {
        const uint4* ap = (const uint4*)&Ah[(size_t)(bm + arow) * 256 + aseg];
        pa0 = ap[0]; pa1 = ap[1];
    }
    pw1 = *(const uint2*)&W1[(size_t)(bn + wrow) * 256 + wseg];
    if (dual) pw2 = *(const uint2*)&W2[(size_t)(bn + wrow) * 256 + wseg];

#pragma unroll 1
    for (int kit = 0; kit < 8; kit++) {
        *(uint4*)&As[arow * 40 + aseg]     = pa0;
        *(uint4*)&As[arow * 40 + aseg + 8] = pa1;
        *(uint2*)&Ws1[wrow * 40 + wseg]    = pw1;
        if (dual) *(uint2*)&Ws2[wrow * 40 + wseg] = pw2;
        __syncthreads();

        if (kit < 7) {
            int k0 = (kit + 1) * 32;
            pa0 = make_uint4(0,0,0,0); pa1 = pa0;
            if (bm + arow < M) {
                const uint4* ap = (const uint4*)&Ah[(size_t)(bm + arow) * 256 + k0 + aseg];
                pa0 = ap[0]; pa1 = ap[1];
            }
            pw1 = *(const uint2*)&W1[(size_t)(bn + wrow) * 256 + k0 + wseg];
            if (dual) pw2 = *(const uint2*)&W2[(size_t)(bn + wrow) * 256 + k0 + wseg];
        }

        uint32_t a0[4], a1[4];
        uint32_t aa = AsB + (uint32_t)((wid * 16 + (lane & 15)) * 40 + ((lane >> 4) * 8)) * 2;
        ldmx4(a0, aa);
        ldmx4(a1, aa + 32);
#pragma unroll
        for (int j = 0; j < 4; j++) {
            uint32_t woff = (uint32_t)((j * 8 + (lane & 7)) * 40 + ((lane >> 3) & 1) * 8) * 2;
            uint32_t b0[2], b1[2];
            ldmx2(b0, W1B + woff);
            ldmx2(b1, W1B + woff + 32);
            mma16816(c1[j], a0, b0);
            mma16816(c1[j], a1, b1);
            if (dual) {
                ldmx2(b0, W2B + woff);
                ldmx2(b1, W2B + woff + 32);
                mma16816(c2[j], a0, b0);
                mma16816(c2[j], a1, b1);
            }
        }
        __syncthreads();
    }

    const int r0 = bm + wid * 16 + (lane >> 2);
    const int cb = 2 * (lane & 3);
    {
        __half* Ca = (__half*)C1;
        __half* Cb = (__half*)C2;
        int ba = r0 / rpb, ra = r0 - ba * rpb;
        int bb = (r0 + 8) / rpb, rb = (r0 + 8) - bb * rpb;
#pragma unroll
        for (int j = 0; j < 4; j++) {
            int col = bn + j * 8 + cb;
            int head = col >> 5, d = col & 31;
            float x0 = b1v[col], x1 = b1v[col + 1];
            if (r0 < M) {
                *(uint32_t*)&Ca[((size_t)((ba * NH + head) * rpb + ra)) * HD + d] =
                    packh2((c1[j][0] + x0) * scale, (c1[j][1] + x1) * scale);
            }
            if (r0 + 8 < M) {
                *(uint32_t*)&Ca[((size_t)((bb * NH + head) * rpb + rb)) * HD + d] =
                    packh2((c1[j][2] + x0) * scale, (c1[j][3] + x1) * scale);
            }
            if (dual) {
                float y0 = b2v[col], y1 = b2v[col + 1];
                if (r0 < M) {
                    *(uint32_t*)&Cb[((size_t)((ba * NH + head) * rpb + ra)) * HD + d] =
                        packh2((c2[j][0] + y0) * scale, (c2[j][1] + y1) * scale);
                }
                if (r0 + 8 < M) {
                    *(uint32_t*)&Cb[((size_t)((bb * NH + head) * rpb + rb)) * HD + d] =
                        packh2((c2[j][2] + y0) * scale, (c2[j][3] + y1) * scale);
                }
            }
        }
    }
}

// ---------------- RPE core ----------------
#define MKFRAG(px, hi0, lo0, hi1, lo1) { \
    float h0 = fmaxf(v0.x - v0.y * (px), 0.f); \
    float h1 = fmaxf(v0.z - v0.w * (px), 0.f); \
    float h2 = fmaxf(v1.x - v1.y * (px), 0.f); \
    float h3 = fmaxf(v1.z - v1.w * (px), 0.f); \
    __half2 t0 = __floats2half2_rn(h0, h1); float2 g0 = __half22float2(t0); \
    __half2 u0 = __floats2half2_rn(h0 - g0.x, h1 - g0.y); \
    __half2 t1 = __floats2half2_rn(h2, h3); float2 g1 = __half22float2(t1); \
    __half2 u1 = __floats2half2_rn(h2 - g1.x, h3 - g1.y); \
    hi0 = *(uint32_t*)&t0; lo0 = *(uint32_t*)&u0; \
    hi1 = *(uint32_t*)&t1; lo1 = *(uint32_t*)&u1; }

__device__ __forceinline__ void rpe_core(char* smem, int q0, int b, int axis,
    const float* __restrict__ refpts,
    const float* __restrict__ w1a, const float* __restrict__ b1a,
    const float* __restrict__ w1b, const float* __restrict__ b1b)
{
    __half* w2hi = (__half*)smem;
    __half* w2lo = (__half*)(smem + 8320);
    float2* as2  = (float2*)(smem + 16640);

    const int tid = threadIdx.x;
    const int lane = tid & 31;
    const int wid = tid >> 5;

    const float* w1  = axis ? w1b : w1a;
    const float* bb1 = axis ? b1b : b1a;
    float* out = axis ? d_rpey : d_rpex;

    const __half* ghi = d_w2hi + axis * 4096;
    const __half* glo = d_w2lo + axis * 4096;
#pragma unroll
    for (int i = tid; i < 2048; i += 256) {
        int h = i >> 8, jj = (i & 255) * 2;
        *(uint32_t*)&w2hi[h * 520 + jj] = *(const uint32_t*)&ghi[h * 512 + jj];
        *(uint32_t*)&w2lo[h * 520 + jj] = *(const uint32_t*)&glo[h * 512 + jj];
    }
#pragma unroll
    for (int i = tid; i < 4 * 512; i += 256) {
        int qi = i >> 9, j = i & 511;
        const float* rp = refpts + ((size_t)b * QLEN + q0 + qi) * 4;
        float cc = rp[axis], ss = rp[2 + axis];
        float lo = (cc - 0.5f * ss) * 1024.f, hi = (cc + 0.5f * ss) * 1024.f;
        float wx = w1[j * 2], wy = w1[j * 2 + 1];
        as2[qi * 512 + j] = make_float2(wx * lo + wy * hi + bb1[j], wx + wy);
    }
    __syncthreads();

    const int qi = wid >> 1;
    const int mt = wid & 1;
    const int q = q0 + qi;
    const int r = lane >> 2;
    const int c0 = 2 * (lane & 3);
    const float pxA = (mt * 16 + r + 0.5f) * 16.f;
    const float pxB = pxA + 128.f;
    const float pxC = pxA + 512.f;
    const float pxD = pxA + 640.f;

    const uint32_t WhiB = smem_u32(w2hi);
    const uint32_t WloB = smem_u32(w2lo);
    const float2* asq = as2 + qi * 512;

    float cA[4] = {0.f, 0.f, 0.f, 0.f};
    float cB[4] = {0.f, 0.f, 0.f, 0.f};

#pragma unroll 4
    for (int kk = 0; kk < 32; kk++) {
        int j0 = kk * 16 + c0;
        float4 v0 = *(const float4*)&asq[j0];
        float4 v1 = *(const float4*)&asq[j0 + 8];

        uint32_t ahiA[4], aloA[4], ahiB[4], aloB[4];
        MKFRAG(pxA, ahiA[0], aloA[0], ahiA[2], aloA[2]);
        MKFRAG(pxB, ahiA[1], aloA[1], ahiA[3], aloA[3]);
        MKFRAG(pxC, ahiB[0], aloB[0], ahiB[2], aloB[2]);
        MKFRAG(pxD, ahiB[1], aloB[1], ahiB[3], aloB[3]);

        uint32_t woff = (uint32_t)((lane & 7) * 520 + kk * 16 + ((lane >> 3) & 1) * 8) * 2;
        uint32_t bhi[2], blo[2];
        ldmx2(bhi, WhiB + woff);
        ldmx2(blo, WloB + woff);
        mma16816(cA, ahiA, bhi);
        mma16816(cA, aloA, bhi);
        mma16816(cA, ahiA, blo);
        mma16816(cB, ahiB, bhi);
        mma16816(cB, aloB, bhi);
        mma16816(cB, ahiB, blo);
    }

    {
        int p0 = mt * 16 + r;
        size_t hstride = (size_t)QLEN * GRD;
        size_t base = ((size_t)(b * NH + c0) * QLEN + q) * GRD;
        out[base + p0]               = cA[0] * L2E;
        out[base + hstride + p0]     = cA[1] * L2E;
        out[base + p0 + 8]           = cA[2] * L2E;
        out[base + hstride + p0 + 8] = cA[3] * L2E;
        out[base + p0 + 32]               = cB[0] * L2E;
        out[base + hstride + p0 + 32]     = cB[1] * L2E;
        out[base + p0 + 40]               = cB[2] * L2E;
        out[base + hstride + p0 + 40]     = cB[3] * L2E;
    }
}

// ---------------- fat mid-kernel ----------------
#define FAT_SMEM 33024
__global__ void __launch_bounds__(256, 4) fat_mid(
    const float* __restrict__ refpts,
    const float* __restrict__ w1a, const float* __restrict__ b1a,
    const float* __restrict__ w1b, const float* __restrict__ b1b,
    const float* __restrict__ qb, const float* __restrict__ kb,
    const float* __restrict__ vb, float qs2)
{
    extern __shared__ char smem[];
    int bx = blockIdx.x;
    if (bx < 900) {
        int axis = bx / 450;
        int rem = bx - axis * 450;
        int b = rem / 225;
        int q0 = (rem % 225) * 4;
        rpe_core(smem, q0, b, axis, refpts, w1a, b1a, w1b, b1b);
    } else if (bx < 1412) {
        int i = bx - 900;
        gemm_core(smem, (i & 63) * 128, (i >> 6) * 32,
                  d_Akv, d_Wh + 65536, kb, d_Kh, d_Wh + 131072, vb, d_Vh,
                  B_ * KVLEN, KVLEN, 1.0f);
    } else {
        int i = bx - 1412;
        gemm_core(smem, (i % 15) * 128, (i / 15) * 32,
                  d_Aq, d_Wh, qb, d_Qh, nullptr, nullptr, nullptr,
                  B_ * QLEN, QLEN, qs2);
    }
}

// ---------------- O projection: 64x32 tile, split-K=2, atomics ----------
__global__ void __launch_bounds__(128) gemm_o64(const float* __restrict__ ob, float* __restrict__ out)
{
    __shared__ __half As[64 * 40];
    __shared__ __half Ws[32 * 40];

    const int tid = threadIdx.x;
    const int lane = tid & 31;
    const int wid = tid >> 5;
    const int bm = blockIdx.x * 64;
    const int bn = blockIdx.y * 32;
    const int kz = blockIdx.z;          // 0/1, each covers k 128
    const int kbase = kz * 128;
    const int M = B_ * QLEN;
    const __half* W1 = d_Wh + 196608;

    const int arow = tid >> 1, aseg = (tid & 1) * 16;
    const int wrow = tid >> 2, wseg = (tid & 3) * 8;

    float c1[4][4];
#pragma unroll
    for (int j = 0; j < 4; j++) { c1[j][0] = c1[j][1] = c1[j][2] = c1[j][3] = 0.f; }

    const uint32_t AsB = smem_u32(As);
    const uint32_t WsB = smem_u32(Ws);

    uint4 pa0 = make_uint4(0,0,0,0), pa1 = pa0;
    uint4 pw;
    if (bm + arow < M) {
        const uint4* ap = (const uint4*)&d_ctxh[(size_t)(bm + arow) * 256 + kbase + aseg];
        pa0 = ap[0]; pa1 = ap[1];
    }
    pw = *(const uint4*)&W1[(size_t)(bn + wrow) * 256 + kbase + wseg];

#pragma unroll 1
    for (int kit = 0; kit < 4; kit++) {
        *(uint4*)&As[arow * 40 + aseg]     = pa0;
        *(uint4*)&As[arow * 40 + aseg + 8] = pa1;
        *(uint4*)&Ws[wrow * 40 + wseg]     = pw;
        __syncthreads();

        if (kit < 3) {
            int k0 = kbase + (kit + 1) * 32;
            pa0 = make_uint4(0,0,0,0); pa1 = pa0;
            if (bm + arow < M) {
                const uint4* ap = (const uint4*)&d_ctxh[(size_t)(bm + arow) * 256 + k0 + aseg];
                pa0 = ap[0]; pa1 = ap[1];
            }
            pw = *(const uint4*)&W1[(size_t)(bn + wrow) * 256 + k0 + wseg];
        }

        uint32_t a0[4], a1[4];
        uint32_t aa = AsB + (uint32_t)((wid * 16 + (lane & 15)) * 40 + ((lane >> 4) * 8)) * 2;
        ldmx4(a0, aa);
        ldmx4(a1, aa + 32);
#pragma unroll
        for (int j = 0; j < 4; j++) {
            uint32_t woff = (uint32_t)((j * 8 + (lane & 7)) * 40 + ((lane >> 3) & 1) * 8) * 2;
            uint32_t b0[2], b1[2];
            ldmx2(b0, WsB + woff);
            ldmx2(b1, WsB + woff + 32);
            mma16816(c1[j], a0, b0);
            mma16816(c1[j], a1, b1);
        }
        __syncthreads();
    }

    const int r0 = bm + wid * 16 + (lane >> 2);
    const int cb = 2 * (lane & 3);
#pragma unroll
    for (int j = 0; j < 4; j++) {
        int col = bn + j * 8 + cb;
        float bb0 = (kz == 0) ? ob[col] : 0.f;
        float bb1 = (kz == 0) ? ob[col + 1] : 0.f;
        if (r0 < M) {
            atomicAdd(&out[(size_t)r0 * 256 + col],     c1[j][0] + bb0);
            atomicAdd(&out[(size_t)r0 * 256 + col + 1], c1[j][1] + bb1);
        }
        if (r0 + 8 < M) {
            atomicAdd(&out[(size_t)(r0 + 8) * 256 + col],     c1[j][2] + bb0);
            atomicAdd(&out[(size_t)(r0 + 8) * 256 + col + 1], c1[j][3] + bb1);
        }
    }
}

// ---------------- split-KV HMMA flash attention (NSPL=8) ------
#define PK 40
#define PRY 12
#define QS_OFF  0
#define KS_OFF  5120
#define VS_OFF  15360
#define RY_OFF  25600
#define MK_OFF  28672
#define ATTN_SMEM 30720

__global__ void __launch_bounds__(128) attn_split()
{
    extern __shared__ char smem[];
    __half* Qs  = (__half*)(smem + QS_OFF);
    float*  rys = (float*)(smem + RY_OFF);
    __half* mks = (__half*)(smem + MK_OFF);

    const int tid = threadIdx.x;
    const int lane = tid & 31;
    const int wid = tid >> 5;
    const int qt = blockIdx.x;
    const int bh = blockIdx.y;
    const int kvh = blockIdx.z;
    const int b = bh >> 3;
    const int q0 = qt * 64;
    const int kv0 = kvh * (KVLEN / NSPL);

    const __half* Kb = d_Kh + (size_t)bh * KVLEN * HD + (size_t)kv0 * HD;
    const __half* Vb = d_Vh + (size_t)bh * KVLEN * HD + (size_t)kv0 * HD;

    const int srow = tid >> 1, sseg = (tid & 1) * 16;
    {
        uint32_t kd = smem_u32(smem + KS_OFF) + (uint32_t)(srow * PK + sseg) * 2;
        uint32_t vd = smem_u32(smem + VS_OFF) + (uint32_t)(srow * PK + sseg) * 2;
        const __half* ks = Kb + (size_t)srow * HD + sseg;
        const __half* vs = Vb + (size_t)srow * HD + sseg;
        CP16(kd, ks); CP16(kd + 16, ks + 8);
        CP16(vd, vs); CP16(vd + 16, vs + 8);
        CP_COMMIT();
    }

    if (tid < 64) {
        const uint4* mg = (const uint4*)(d_mskh + b * KVLEN + kv0);
        ((uint4*)mks)[tid] = mg[tid];
    }

    {
        int row = tid >> 1, seg = tid & 1;
        int q = q0 + row;
        uint4 v0 = make_uint4(0, 0, 0, 0), v1 = make_uint4(0, 0, 0, 0);
        if (q < QLEN) {
            const uint4* qp = (const uint4*)(d_Qh + ((size_t)bh * QLEN + q) * HD + seg * 16);
            v0 = qp[0]; v1 = qp[1];
        }
        *(uint4*)(Qs + row * PK + seg * 16)     = v0;
        *(uint4*)(Qs + row * PK + seg * 16 + 8) = v1;
    }
    // ry: 8 values per q row (this eighth's grid rows)
    {
        int row = tid >> 1, sb = (tid & 1) * 4;
        int q = q0 + row;
        float4 v = make_float4(0.f, 0.f, 0.f, 0.f);
        if (q < QLEN)
            v = *(const float4*)(d_rpey + ((size_t)bh * QLEN + q) * GRD + kvh * 8 + sb);
        *(float4*)(rys + row * PRY + sb) = v;
    }
    __syncthreads();

    uint32_t aQ[2][4];
    {
        uint32_t base = smem_u32(Qs);
        int m = wid * 16 + (lane & 15);
        uint32_t a0 = base + (uint32_t)(m * PK + ((lane >> 4) * 8)) * 2;
        ldmx4(aQ[0], a0);
        ldmx4(aQ[1], a0 + 32);
    }

    const int r0 = wid * 16 + (lane >> 2);
    const int cb = 2 * (lane & 3);

    float2 rxa[8], rxb[8];
    {
        int qa = q0 + r0, qb2 = qa + 8;
        const float* rxg = d_rpex + (size_t)bh * QLEN * GRD;
        float2 z = make_float2(0.f, 0.f);
#pragma unroll
        for (int j = 0; j < 8; j++) {
            int n = j * 8 + cb;
            rxa[j] = (qa  < QLEN) ? *(const float2*)&rxg[(size_t)qa  * GRD + n] : z;
            rxb[j] = (qb2 < QLEN) ? *(const float2*)&rxg[(size_t)qb2 * GRD + n] : z;
        }
    }

    float oc[4][4];
#pragma unroll
    for (int i = 0; i < 4; i++)
#pragma unroll
        for (int j = 0; j < 4; j++) oc[i][j] = 0.f;
    float m_run0 = -1e30f, m_run1 = -1e30f, l_run0 = 0.f, l_run1 = 0.f;

    const int NT = KVLEN / NSPL / 64;  // 8 tiles
    for (int t = 0; t < NT; t++) {
        CP_WAIT0();
        __syncthreads();
        if (t + 1 < NT) {
            int buf = (t + 1) & 1;
            uint32_t kd = smem_u32(smem + KS_OFF + buf * 5120) + (uint32_t)(srow * PK + sseg) * 2;
            uint32_t vd = smem_u32(smem + VS_OFF + buf * 5120) + (uint32_t)(srow * PK + sseg) * 2;
            const __half* ks = Kb + (size_t)((t + 1) * 64 + srow) * HD + sseg;
            const __half* vs = Vb + (size_t)((t + 1) * 64 + srow) * HD + sseg;
            CP16(kd, ks); CP16(kd + 16, ks + 8);
            CP16(vd, vs); CP16(vd + 16, vs + 8);
            CP_COMMIT();
        }

        const uint32_t KsB = smem_u32(smem + KS_OFF + (t & 1) * 5120);
        const uint32_t VsB = smem_u32(smem + VS_OFF + (t & 1) * 5120);

        float sc[8][4];
#pragma unroll
        for (int j = 0; j < 8; j++) {
            sc[j][0] = sc[j][1] = sc[j][2] = sc[j][3] = 0.f;
            uint32_t addr = KsB + (uint32_t)((j * 8 + (lane & 7)) * PK + ((lane >> 3) & 1) * 8) * 2;
            uint32_t bk0[2], bk1[2];
            ldmx2(bk0, addr);
            ldmx2(bk1, addr + 32);
            mma16816(sc[j], aQ[0], bk0);
            mma16816(sc[j], aQ[1], bk1);
        }

        float mx0 = -1e30f, mx1 = -1e30f;
#pragma unroll
        for (int j = 0; j < 8; j++) {
            int n = j * 8 + cb;
            float2 mk = __half22float2(*(__half2*)(mks + t * 64 + n));
            sc[j][0] += rxa[j].x + mk.x;
            sc[j][1] += rxa[j].y + mk.y;
            sc[j][2] += rxb[j].x + mk.x;
            sc[j][3] += rxb[j].y + mk.y;
            mx0 = fmaxf(mx0, fmaxf(sc[j][0], sc[j][1]));
            mx1 = fmaxf(mx1, fmaxf(sc[j][2], sc[j][3]));
        }
        mx0 = fmaxf(mx0, __shfl_xor_sync(0xffffffffu, mx0, 1));
        mx0 = fmaxf(mx0, __shfl_xor_sync(0xffffffffu, mx0, 2));
        mx1 = fmaxf(mx1, __shfl_xor_sync(0xffffffffu, mx1, 1));
        mx1 = fmaxf(mx1, __shfl_xor_sync(0xffffffffu, mx1, 2));

        float ry0 = rys[r0 * PRY + t];
        float ry1 = rys[(r0 + 8) * PRY + t];
        float mn0 = fmaxf(m_run0, mx0 + ry0), mn1 = fmaxf(m_run1, mx1 + ry1);
        float base0 = mn0 - ry0, base1 = mn1 - ry1;
        float f0 = ex2(m_run0 - mn0), f1 = ex2(m_run1 - mn1);
        m_run0 = mn0; m_run1 = mn1;

        float la0 = 0.f, la1 = 0.f;
        uint32_t pa[4][4];
#pragma unroll
        for (int j = 0; j < 8; j++) {
            float p0 = ex2(sc[j][0] - base0);
            float p1 = ex2(sc[j][1] - base0);
            float p2 = ex2(sc[j][2] - base1);
            float p3 = ex2(sc[j][3] - base1);
            la0 += p0 + p1; la1 += p2 + p3;
            int kt = j >> 1, hi = j & 1;
            pa[kt][2 * hi]     = packh2(p0, p1);
            pa[kt][2 * hi + 1] = packh2(p2, p3);
        }
        l_run0 = l_run0 * f0 + la0;
        l_run1 = l_run1 * f1 + la1;

#pragma unroll
        for (int no = 0; no < 4; no++) {
            oc[no][0] *= f0; oc[no][1] *= f0;
            oc[no][2] *= f1; oc[no][3] *= f1;
        }

#pragma unroll
        for (int kt = 0; kt < 4; kt++) {
            uint32_t addr = VsB + (uint32_t)((kt * 16 + (lane & 15)) * PK) * 2;
#pragma unroll
            for (int no = 0; no < 4; no++) {
                uint32_t bv[2];
                ldmx2t(bv, addr + (uint32_t)(no * 8) * 2);
                mma16816(oc[no], pa[kt], bv);
            }
        }
    }

    // final quad reduction of l
    l_run0 += __shfl_xor_sync(0xffffffffu, l_run0, 1);
    l_run0 += __shfl_xor_sync(0xffffffffu, l_run0, 2);
    l_run1 += __shfl_xor_sync(0xffffffffu, l_run1, 1);
    l_run1 += __shfl_xor_sync(0xffffffffu, l_run1, 2);

    // write partials (normalized, f16)
    {
        int cta = (bh * NQT + qt) * NSPL + kvh;
        __half* po = d_poh + (size_t)cta * 2048;
        float inv0 = 1.0f / l_run0;
        float inv1 = 1.0f / l_run1;
#pragma unroll
        for (int no = 0; no < 4; no++) {
            int d = no * 8 + cb;
            *(uint32_t*)&po[r0 * 32 + d]       = packh2(oc[no][0] * inv0, oc[no][1] * inv0);
            *(uint32_t*)&po[(r0 + 8) * 32 + d] = packh2(oc[no][2] * inv1, oc[no][3] * inv1);
        }
        if ((lane & 3) == 0) {
            d_pm[cta * 64 + r0]     = m_run0;
            d_pm[cta * 64 + r0 + 8] = m_run1;
            d_pl[cta * 64 + r0]     = l_run0;
            d_pl[cta * 64 + r0 + 8] = l_run1;
        }
    }
}

// ---------------- merge partials -> ctx f16 ----------------
__global__ void __launch_bounds__(256) attn_merge()
{
    const int bx = blockIdx.x;         // bh * NQT + qt
    const int bh = bx / NQT;
    const int qt = bx - bh * NQT;
    const int b = bh >> 3;
    const int head = bh & 7;
    const int ql = (threadIdx.x >> 3) + blockIdx.y * 32;   // 0..63
    const int du = threadIdx.x & 7;    // 4-dim chunk
    const int q = qt * 64 + ql;
    if (q >= QLEN) return;

    const int c0 = bx * NSPL;
    float ms[NSPL], ls[NSPL];
    float m = -1e30f;
#pragma unroll
    for (int s = 0; s < NSPL; s++) {
        ms[s] = d_pm[(c0 + s) * 64 + ql];
        ls[s] = d_pl[(c0 + s) * 64 + ql];
        m = fmaxf(m, ms[s]);
    }
    float ws[NSPL], lsum = 0.f;
#pragma unroll
    for (int s = 0; s < NSPL; s++) { ws[s] = ls[s] * ex2(ms[s] - m); lsum += ws[s]; }
    float inv = 1.0f / lsum;

    float acc[4] = {0.f, 0.f, 0.f, 0.f};
#pragma unroll
    for (int s = 0; s < NSPL; s++) {
        const uint2* o = (const uint2*)(d_poh + (size_t)(c0 + s) * 2048 + ql * 32 + du * 4);
        uint2 v = o[0];
        float2 a = __half22float2(*(__half2*)&v.x);
        float2 c = __half22float2(*(__half2*)&v.y);
        float f = ws[s] * inv;
        acc[0] += a.x * f; acc[1] += a.y * f;
        acc[2] += c.x * f; acc[3] += c.y * f;
    }
    uint2 w;
    w.x = packh2(acc[0], acc[1]); w.y = packh2(acc[2], acc[3]);
    *(uint2*)(d_ctxh + ((size_t)b * QLEN + q) * DIMV + head * HD + du * 4) = w;
}

// ---------------- launch ----------------
extern "C" void kernel_launch(void* const* d_in, const int* in_sizes, int n_in,
                              void* d_out, int out_size)
{
    const float* hidden = (const float*)d_in[0];
    const float* refpts = (const float*)d_in[1];
    const float* kvst   = (const float*)d_in[2];
    const int*   amask  = (const int*)d_in[4];
    const float* m1w1 = (const float*)d_in[5];
    const float* m1b1 = (const float*)d_in[6];
    const float* m1w2 = (const float*)d_in[7];
    const float* m2w1 = (const float*)d_in[8];
    const float* m2b1 = (const float*)d_in[9];
    const float* m2w2 = (const float*)d_in[10];
    const float* qw = (const float*)d_in[11];
    const float* qb = (const float*)d_in[12];
    const float* kw = (const float*)d_in[13];
    const float* kb = (const float*)d_in[14];
    const float* vw = (const float*)d_in[15];
    const float* vb = (const float*)d_in[16];
    const float* ow = (const float*)d_in[17];
    const float* ob = (const float*)d_in[18];
    float* out = (float*)d_out;

    cudaFuncSetAttribute(attn_split, cudaFuncAttributeMaxDynamicSharedMemorySize, ATTN_SMEM);

    const float qs2 = 0.17677669529663687f * L2E;

    convert_all<<<3220, 256>>>(qw, kw, vw, ow, kvst, hidden, m1w2, m2w2, amask, out);
    fat_mid<<<1532, 256, FAT_SMEM>>>(refpts, m1w1, m1b1, m2w1, m2b1, qb, kb, vb, qs2);
    attn_split<<<dim3(NQT, B_ * NH, NSPL), 128, ATTN_SMEM>>>();
    attn_merge<<<dim3(16 * NQT, 2), 256>>>();
    gemm_o64<<<dim3(29, 8, 2), 128>>>(ob, out);
}